// round 9
// baseline (speedup 1.0000x reference)
#include <cuda_runtime.h>

// out[n, d] = sum_k mat[n,k] * feat[graph[n,k], d]
// N=40000, K=32, D=64. One warp per item n.
//
// Index dtype is ambiguous (reference says int64; JAX w/o x64 dumps int32).
// A one-block probe kernel disambiguates at runtime: viewing the buffer as
// int32 words, int64 data with values < 2^31 has ALL odd words == 0;
// int32 data has uniform random indices in odd slots. Probe sets g_idx_is_i64.
// Sampling stays within the first n_elems words — in-bounds under BOTH
// interpretations (int32 buffer: exactly n words; int64 buffer: 2n words).
//
// Gather kernel: lane l owns output elements [2l, 2l+1] (float2). Each lane
// preloads its (index, weight) pair; 32 fully-unrolled shfl-broadcast steps,
// each a coalesced 256B/warp float2 gather of one neighbor row (L2-resident).

#define K_NEIGH 32
#define D_LAT   64

__device__ int g_idx_is_i64;

__global__ void detect_idx_dtype_kernel(const int* __restrict__ graph_i32,
                                        int n_elems)
{
    __shared__ int s_nonzero;
    if (threadIdx.x == 0) s_nonzero = 0;
    __syncthreads();

    int found = 0;
    const int samples = 8192;
    // Sample odd words strictly within [0, n_elems) 32-bit words.
    const int n_pairs = n_elems / 2;          // pairs fully inside n_elems words
    for (int s = threadIdx.x; s < samples; s += blockDim.x) {
        long long pair = ((long long)s * n_pairs) / samples;   // pair < n_pairs
        int word = (int)(2 * pair + 1);                        // odd word < n_elems
        if (graph_i32[word] != 0) found = 1;
    }
    if (found) atomicOr(&s_nonzero, 1);
    __syncthreads();
    if (threadIdx.x == 0) g_idx_is_i64 = (s_nonzero == 0) ? 1 : 0;
}

__global__ void __launch_bounds__(256)
item_graph_sample_kernel(const float* __restrict__ feat,
                         const void* __restrict__ graph_raw,
                         const float* __restrict__ mat,
                         float* __restrict__ out,
                         int n_items)
{
    const int warp_id = (blockIdx.x * blockDim.x + threadIdx.x) >> 5;
    const int lane    = threadIdx.x & 31;
    if (warp_id >= n_items) return;

    const int is_i64 = g_idx_is_i64;

    // Coalesced load of this item's 32 indices + 32 weights (one per lane).
    long long my_idx;
    if (is_i64) {
        my_idx = ((const long long*)graph_raw)[warp_id * K_NEIGH + lane];
    } else {
        my_idx = (long long)((const int*)graph_raw)[warp_id * K_NEIGH + lane];
    }
    const float my_w = mat[warp_id * K_NEIGH + lane];

    float2 acc = make_float2(0.0f, 0.0f);

    // Fully unrolled: 32 independent LDG.64 gathers in flight per warp.
    #pragma unroll
    for (int k = 0; k < K_NEIGH; ++k) {
        const long long idx = __shfl_sync(0xffffffffu, my_idx, k);
        const float     w   = __shfl_sync(0xffffffffu, my_w,   k);
        const float2 v = __ldg(reinterpret_cast<const float2*>(
            feat + idx * D_LAT + 2 * lane));
        acc.x = fmaf(w, v.x, acc.x);
        acc.y = fmaf(w, v.y, acc.y);
    }

    *reinterpret_cast<float2*>(out + (long long)warp_id * D_LAT + 2 * lane) = acc;
}

extern "C" void kernel_launch(void* const* d_in, const int* in_sizes, int n_in,
                              void* d_out, int out_size)
{
    const float* feat  = (const float*)d_in[0];  // [N, 64] f32
    const void*  graph = d_in[1];                // [N, 32] i32 or i64
    const float* mat   = (const float*)d_in[2];  // [N, 32] f32
    float*       out   = (float*)d_out;          // [N, 64] f32

    const int n_idx_elems = in_sizes[1];         // 40000*32 index elements
    const int n_items     = in_sizes[2] / K_NEIGH;

    detect_idx_dtype_kernel<<<1, 1024>>>((const int*)graph, n_idx_elems);

    const int threads = 256;                 // 8 warps = 8 items per CTA
    const int items_per_block = threads / 32;
    const int blocks = (n_items + items_per_block - 1) / items_per_block;

    item_graph_sample_kernel<<<blocks, threads>>>(feat, graph, mat, out, n_items);
}

// round 11
// speedup vs baseline: 1.1209x; 1.1209x over previous
#include <cuda_runtime.h>

// out[n, d] = sum_k mat[n,k] * feat[graph[n,k], d]
// N=40000, K=32, D=64. One warp per item n.
//
// Index dtype probe (1 warp, 64 samples): viewing the buffer as int32 words,
// int64 data with values < 2^31 has ALL odd words == 0; int32 data has
// uniform random indices there. Samples stay within the first n_elems words,
// in-bounds under BOTH interpretations.
//
// Gather kernel: lane l owns output elements [2l, 2l+1] (float2); 32
// fully-unrolled shfl-broadcast steps, each a coalesced 256B/warp float2
// gather. __ldcg bypasses L1 allocation: gathers are ~all L1 misses (random
// rows, 228KB L1 vs 10MB table), and skipping the L1 fill-write halves L1
// data-bank work (measured l1tex 75.3% >> lts 47.8% with default caching).

#define K_NEIGH 32
#define D_LAT   64

__device__ int g_idx_is_i64;

__global__ void detect_idx_dtype_kernel(const int* __restrict__ graph_i32,
                                        int n_elems)
{
    const int lane = threadIdx.x;            // 32 threads, 64 samples
    const int n_pairs = n_elems / 2;         // pairs fully inside n_elems words
    int found = 0;
    #pragma unroll
    for (int j = 0; j < 2; ++j) {
        int s = lane * 2 + j;                                  // 0..63
        long long pair = ((long long)s * n_pairs) / 64;        // pair < n_pairs
        int word = (int)(2 * pair + 1);                        // odd word < n_elems
        if (graph_i32[word] != 0) found = 1;
    }
    unsigned any = __ballot_sync(0xffffffffu, found);
    if (lane == 0) g_idx_is_i64 = (any == 0) ? 1 : 0;
}

__global__ void __launch_bounds__(256)
item_graph_sample_kernel(const float* __restrict__ feat,
                         const void* __restrict__ graph_raw,
                         const float* __restrict__ mat,
                         float* __restrict__ out,
                         int n_items)
{
    const int warp_id = (blockIdx.x * blockDim.x + threadIdx.x) >> 5;
    const int lane    = threadIdx.x & 31;
    if (warp_id >= n_items) return;

    const int is_i64 = g_idx_is_i64;

    // Coalesced load of this item's 32 indices + 32 weights (one per lane).
    long long my_idx;
    if (is_i64) {
        my_idx = ((const long long*)graph_raw)[warp_id * K_NEIGH + lane];
    } else {
        my_idx = (long long)((const int*)graph_raw)[warp_id * K_NEIGH + lane];
    }
    const float my_w = mat[warp_id * K_NEIGH + lane];

    float2 acc = make_float2(0.0f, 0.0f);

    // Fully unrolled: 32 independent L2-cached (L1-bypass) gathers in flight.
    #pragma unroll
    for (int k = 0; k < K_NEIGH; ++k) {
        const long long idx = __shfl_sync(0xffffffffu, my_idx, k);
        const float     w   = __shfl_sync(0xffffffffu, my_w,   k);
        const float2 v = __ldcg(reinterpret_cast<const float2*>(
            feat + idx * D_LAT + 2 * lane));
        acc.x = fmaf(w, v.x, acc.x);
        acc.y = fmaf(w, v.y, acc.y);
    }

    *reinterpret_cast<float2*>(out + (long long)warp_id * D_LAT + 2 * lane) = acc;
}

extern "C" void kernel_launch(void* const* d_in, const int* in_sizes, int n_in,
                              void* d_out, int out_size)
{
    const float* feat  = (const float*)d_in[0];  // [N, 64] f32
    const void*  graph = d_in[1];                // [N, 32] i32 or i64
    const float* mat   = (const float*)d_in[2];  // [N, 32] f32
    float*       out   = (float*)d_out;          // [N, 64] f32

    const int n_idx_elems = in_sizes[1];         // 40000*32 index elements
    const int n_items     = in_sizes[2] / K_NEIGH;

    detect_idx_dtype_kernel<<<1, 32>>>((const int*)graph, n_idx_elems);

    const int threads = 256;                 // 8 warps = 8 items per CTA
    const int items_per_block = threads / 32;
    const int blocks = (n_items + items_per_block - 1) / items_per_block;

    item_graph_sample_kernel<<<blocks, threads>>>(feat, graph, mat, out, n_items);
}

// round 12
// speedup vs baseline: 1.3980x; 1.2471x over previous
#include <cuda_runtime.h>

// out[n, d] = sum_k mat[n,k] * feat[graph[n,k], d]
// N=40000, K=32, D=64. One warp per item n. Single kernel, no probe launch.
//
// Inline per-warp dtype detection: load the warp's 32-word window as int32
// (in-bounds under BOTH dtypes), ballot odd lanes. int64 data (values<2^31)
// has all odd words == 0 -> reload as int64; int32 data has 16 uniform random
// indices there (P(all zero) = (1/40000)^16 ~ 0).
//
// Gather: lanes split in halves; half h handles neighbor 2k+h at step k.
// Each lane loads float4 (dims 4*sub..4*sub+3) -> 16 LDG.128 per item instead
// of 32 LDG.64: same sector traffic, half the L1tex wavefront/issue work,
// ~2.7x in-flight bytes per warp (R11: regs=32 had register-throttled MLP).
// shfl_xor(16) combines even/odd partial sums; half-warp float4 __stcg store.

#define K_NEIGH 32
#define D_LAT   64

__global__ void __launch_bounds__(256)
item_graph_sample_kernel(const float* __restrict__ feat,
                         const void* __restrict__ graph_raw,
                         const float* __restrict__ mat,
                         float* __restrict__ out,
                         int n_items)
{
    const int warp_id = (blockIdx.x * blockDim.x + threadIdx.x) >> 5;
    const int lane    = threadIdx.x & 31;
    if (warp_id >= n_items) return;

    const int half = lane >> 4;      // 0: even neighbors, 1: odd neighbors
    const int sub  = lane & 15;      // dim group: owns dims [4*sub, 4*sub+3]

    // --- inline dtype detection + index load (coalesced) ---
    const int my_i32 = ((const int*)graph_raw)[warp_id * K_NEIGH + lane];
    const unsigned nz = __ballot_sync(0xffffffffu, my_i32 != 0);
    const bool is_i64 = ((nz & 0xAAAAAAAAu) == 0u);   // all odd words zero

    long long my_idx;
    if (is_i64) {
        my_idx = ((const long long*)graph_raw)[warp_id * K_NEIGH + lane];
    } else {
        my_idx = (long long)my_i32;
    }
    const float my_w = mat[warp_id * K_NEIGH + lane];

    float4 acc = make_float4(0.0f, 0.0f, 0.0f, 0.0f);

    // 16 steps; each step gathers two neighbor rows (512B/warp, LDG.128).
    #pragma unroll
    for (int k = 0; k < K_NEIGH / 2; ++k) {
        const int src = 2 * k + half;
        const long long idx = __shfl_sync(0xffffffffu, my_idx, src);
        const float     w   = __shfl_sync(0xffffffffu, my_w,   src);
        const float4 v = __ldg(reinterpret_cast<const float4*>(
            feat + idx * D_LAT + 4 * sub));
        acc.x = fmaf(w, v.x, acc.x);
        acc.y = fmaf(w, v.y, acc.y);
        acc.z = fmaf(w, v.z, acc.z);
        acc.w = fmaf(w, v.w, acc.w);
    }

    // Combine even-half (lanes 0-15) with odd-half (lanes 16-31).
    acc.x += __shfl_xor_sync(0xffffffffu, acc.x, 16);
    acc.y += __shfl_xor_sync(0xffffffffu, acc.y, 16);
    acc.z += __shfl_xor_sync(0xffffffffu, acc.z, 16);
    acc.w += __shfl_xor_sync(0xffffffffu, acc.w, 16);

    if (half == 0) {
        __stcg(reinterpret_cast<float4*>(
                   out + (long long)warp_id * D_LAT + 4 * sub), acc);
    }
}

extern "C" void kernel_launch(void* const* d_in, const int* in_sizes, int n_in,
                              void* d_out, int out_size)
{
    const float* feat  = (const float*)d_in[0];  // [N, 64] f32
    const void*  graph = d_in[1];                // [N, 32] i32 or i64
    const float* mat   = (const float*)d_in[2];  // [N, 32] f32
    float*       out   = (float*)d_out;          // [N, 64] f32

    const int n_items = in_sizes[2] / K_NEIGH;   // 40000

    const int threads = 256;                 // 8 warps = 8 items per CTA
    const int items_per_block = threads / 32;
    const int blocks = (n_items + items_per_block - 1) / items_per_block;

    item_graph_sample_kernel<<<blocks, threads>>>(feat, graph, mat, out, n_items);
}